// round 1
// baseline (speedup 1.0000x reference)
#include <cuda_runtime.h>
#include <cuda_bf16.h>
#include <stdint.h>

// Problem constants: B=S=H=DH=64, D = H*DH = 4096
static const int DFEAT = 4096;   // d_feature
static const int NTOK  = 4096;   // B*S tokens (also B*H rows for output proj)

// GEMM tiling
static const int BM = 128;
static const int BN = 128;
static const int BKF = 16;       // fp32 k per mainloop iter
static const int SK  = 24;       // padded smem k-stride (conflict-free frag loads)
static const int NKI = DFEAT / BKF;  // 256 iterations

// Scratch (no cudaMalloc allowed): q,k,v (3 x 4096 x 4096 f32) + merged (4096 x 4096 f32)
__device__ float g_qkv[3ull * (size_t)NTOK * DFEAT];
__device__ float g_merged[(size_t)NTOK * DFEAT];

struct GemmArgs {
    const float* A;
    const float* W[3];
    const float* bias[3];
    float*       C[3];
};

// m16n8k16 row.col bf16 mma, fp32 accumulate
__device__ __forceinline__ void mma_bf16(float c[4], const uint32_t a[4], const uint32_t b[2]) {
    asm volatile(
        "mma.sync.aligned.m16n8k16.row.col.f32.bf16.bf16.f32 "
        "{%0,%1,%2,%3}, {%4,%5,%6,%7}, {%8,%9}, {%0,%1,%2,%3};\n"
        : "+f"(c[0]), "+f"(c[1]), "+f"(c[2]), "+f"(c[3])
        : "r"(a[0]), "r"(a[1]), "r"(a[2]), "r"(a[3]), "r"(b[0]), "r"(b[1]));
}

// Split a float4 into hi/lo bf16 pairs and store (4 consecutive elements each).
__device__ __forceinline__ void split_store4(__nv_bfloat16* hip, __nv_bfloat16* lop, float4 v) {
    __nv_bfloat16 h0 = __float2bfloat16(v.x);
    __nv_bfloat16 h1 = __float2bfloat16(v.y);
    __nv_bfloat16 h2 = __float2bfloat16(v.z);
    __nv_bfloat16 h3 = __float2bfloat16(v.w);
    __nv_bfloat16 l0 = __float2bfloat16(v.x - __bfloat162float(h0));
    __nv_bfloat16 l1 = __float2bfloat16(v.y - __bfloat162float(h1));
    __nv_bfloat16 l2 = __float2bfloat16(v.z - __bfloat162float(h2));
    __nv_bfloat16 l3 = __float2bfloat16(v.w - __bfloat162float(h3));
    __nv_bfloat162* hp = reinterpret_cast<__nv_bfloat162*>(hip);
    __nv_bfloat162* lp = reinterpret_cast<__nv_bfloat162*>(lop);
    hp[0] = __halves2bfloat162(h0, h1);
    hp[1] = __halves2bfloat162(h2, h3);
    lp[0] = __halves2bfloat162(l0, l1);
    lp[1] = __halves2bfloat162(l2, l3);
}

// C[m][n] = sum_k A[m][k] * W[n][k] + bias[n], M = N = K = 4096.
// bf16x3: acc += Ahi*Whi + Ahi*Wlo + Alo*Whi   (error ~2^-17 per product)
__global__ __launch_bounds__(256, 2) void gemm_kernel(GemmArgs args) {
    __shared__ __nv_bfloat16 sA[2][BM][SK];  // [hi/lo][row][k]
    __shared__ __nv_bfloat16 sB[2][BN][SK];

    const int z = blockIdx.z;
    const float* __restrict__ A    = args.A;
    const float* __restrict__ W    = args.W[z];
    const float* __restrict__ bias = args.bias[z];
    float* __restrict__       C    = args.C[z];

    const int tid = threadIdx.x;
    const int bm = blockIdx.y * BM;
    const int bn = blockIdx.x * BN;

    // gmem load mapping: 128x16 tile = 512 float4 chunks; 256 threads x 2
    const int arow = tid >> 2;   // 0..63
    const int ac4  = tid & 3;    // float4 column within 16
    const float* Ap0 = A + (size_t)(bm + arow) * DFEAT + ac4 * 4;
    const float* Ap1 = Ap0 + (size_t)64 * DFEAT;
    const float* Bp0 = W + (size_t)(bn + arow) * DFEAT + ac4 * 4;
    const float* Bp1 = Bp0 + (size_t)64 * DFEAT;

    const int wid  = tid >> 5;
    const int lane = tid & 31;
    const int g  = lane >> 2;    // group id 0..7
    const int tg = lane & 3;     // thread-in-group 0..3
    const int wm = (wid & 1) * 64;   // 2 warps along M (64 rows each)
    const int wn = (wid >> 1) * 32;  // 4 warps along N (32 cols each)

    float acc[4][4][4];
    #pragma unroll
    for (int a0 = 0; a0 < 4; ++a0)
        #pragma unroll
        for (int b0 = 0; b0 < 4; ++b0)
            #pragma unroll
            for (int c0 = 0; c0 < 4; ++c0) acc[a0][b0][c0] = 0.0f;

    // prologue load
    float4 ra0 = *(const float4*)Ap0;
    float4 ra1 = *(const float4*)Ap1;
    float4 rb0 = *(const float4*)Bp0;
    float4 rb1 = *(const float4*)Bp1;

    for (int kt = 0; kt < NKI; ++kt) {
        __syncthreads();
        split_store4(&sA[0][arow][ac4 * 4],      &sA[1][arow][ac4 * 4],      ra0);
        split_store4(&sA[0][arow + 64][ac4 * 4], &sA[1][arow + 64][ac4 * 4], ra1);
        split_store4(&sB[0][arow][ac4 * 4],      &sB[1][arow][ac4 * 4],      rb0);
        split_store4(&sB[0][arow + 64][ac4 * 4], &sB[1][arow + 64][ac4 * 4], rb1);
        __syncthreads();

        if (kt + 1 < NKI) {  // prefetch next k-slab while mma runs
            const int off = (kt + 1) * BKF;
            ra0 = *(const float4*)(Ap0 + off);
            ra1 = *(const float4*)(Ap1 + off);
            rb0 = *(const float4*)(Bp0 + off);
            rb1 = *(const float4*)(Bp1 + off);
        }

        // B fragments (hi/lo) for 4 n-tiles
        uint32_t bh[4][2], bl[4][2];
        #pragma unroll
        for (int nt = 0; nt < 4; ++nt) {
            const int n = wn + nt * 8 + g;
            bh[nt][0] = *(const uint32_t*)&sB[0][n][tg * 2];
            bh[nt][1] = *(const uint32_t*)&sB[0][n][tg * 2 + 8];
            bl[nt][0] = *(const uint32_t*)&sB[1][n][tg * 2];
            bl[nt][1] = *(const uint32_t*)&sB[1][n][tg * 2 + 8];
        }

        #pragma unroll
        for (int mt = 0; mt < 4; ++mt) {
            const int r = wm + mt * 16 + g;
            uint32_t ah[4], al[4];
            ah[0] = *(const uint32_t*)&sA[0][r][tg * 2];
            ah[1] = *(const uint32_t*)&sA[0][r + 8][tg * 2];
            ah[2] = *(const uint32_t*)&sA[0][r][tg * 2 + 8];
            ah[3] = *(const uint32_t*)&sA[0][r + 8][tg * 2 + 8];
            al[0] = *(const uint32_t*)&sA[1][r][tg * 2];
            al[1] = *(const uint32_t*)&sA[1][r + 8][tg * 2];
            al[2] = *(const uint32_t*)&sA[1][r][tg * 2 + 8];
            al[3] = *(const uint32_t*)&sA[1][r + 8][tg * 2 + 8];
            #pragma unroll
            for (int nt = 0; nt < 4; ++nt) {
                mma_bf16(acc[mt][nt], ah, bh[nt]);  // hi*hi
                mma_bf16(acc[mt][nt], ah, bl[nt]);  // hi*lo
                mma_bf16(acc[mt][nt], al, bh[nt]);  // lo*hi
            }
        }
    }

    // epilogue: bias + fp32 store
    #pragma unroll
    for (int mt = 0; mt < 4; ++mt) {
        #pragma unroll
        for (int nt = 0; nt < 4; ++nt) {
            const int r0 = bm + wm + mt * 16 + g;
            const int c0 = bn + wn + nt * 8 + tg * 2;
            const float bx = bias[c0];
            const float by = bias[c0 + 1];
            *(float2*)&C[(size_t)r0 * DFEAT + c0] =
                make_float2(acc[mt][nt][0] + bx, acc[mt][nt][1] + by);
            *(float2*)&C[(size_t)(r0 + 8) * DFEAT + c0] =
                make_float2(acc[mt][nt][2] + bx, acc[mt][nt][3] + by);
        }
    }
}

// Per-token attention over the HEAD axis. One CTA per token m = b*64+s.
// scores[i][e] = q[i]·k[e] / 8 ; attn = softmax_e ; vals[i][j] = sum_k attn[i][k] v[j][k]
// merged[(b*64+i)][s*64+j] = vals[i][j]
__global__ __launch_bounds__(256) void attn_kernel(const float* __restrict__ qkv,
                                                   float* __restrict__ merged) {
    __shared__ float qs[64][64];   // phase1: q rows; phase2: attn
    __shared__ float kb[64][68];   // phase1: k rows; phase2: v rows (padded stride)

    const int m = blockIdx.x;
    const int b = m >> 6;
    const int s = m & 63;
    const int tid = threadIdx.x;

    const float* Qp = qkv + (size_t)m * DFEAT;
    const float* Kp = Qp + (size_t)NTOK * DFEAT;
    const float* Vp = Kp + (size_t)NTOK * DFEAT;

    #pragma unroll
    for (int i = 0; i < 4; ++i) {
        const int l = tid + i * 256;
        const int h = l >> 4;
        const int dc = (l & 15) * 4;
        *(float4*)&qs[h][dc] = *(const float4*)(Qp + h * 64 + dc);
        *(float4*)&kb[h][dc] = *(const float4*)(Kp + h * 64 + dc);
    }
    __syncthreads();

    const int ty = tid >> 4;      // 0..15 -> row block i0 = ty*4
    const int tx = tid & 15;      // e columns {tx, tx+16, tx+32, tx+48}
    const int i0 = ty * 4;

    float sc[4][4];
    #pragma unroll
    for (int r = 0; r < 4; ++r)
        #pragma unroll
        for (int c = 0; c < 4; ++c) sc[r][c] = 0.0f;

    #pragma unroll
    for (int d4 = 0; d4 < 16; ++d4) {
        float4 qv[4], kv[4];
        #pragma unroll
        for (int r = 0; r < 4; ++r) qv[r] = *(const float4*)&qs[i0 + r][d4 * 4];
        #pragma unroll
        for (int c = 0; c < 4; ++c) kv[c] = *(const float4*)&kb[tx + 16 * c][d4 * 4];
        #pragma unroll
        for (int r = 0; r < 4; ++r)
            #pragma unroll
            for (int c = 0; c < 4; ++c)
                sc[r][c] += qv[r].x * kv[c].x + qv[r].y * kv[c].y +
                            qv[r].z * kv[c].z + qv[r].w * kv[c].w;
    }
    __syncthreads();  // all reads of q/k done

    // softmax per row (row i0+r owned by the 16 tx lanes of this ty)
    #pragma unroll
    for (int r = 0; r < 4; ++r) {
        #pragma unroll
        for (int c = 0; c < 4; ++c) sc[r][c] *= 0.125f;  // 1/sqrt(64)
        float mx = fmaxf(fmaxf(sc[r][0], sc[r][1]), fmaxf(sc[r][2], sc[r][3]));
        #pragma unroll
        for (int off = 8; off >= 1; off >>= 1)
            mx = fmaxf(mx, __shfl_xor_sync(0xffffffffu, mx, off));
        float sum = 0.0f;
        #pragma unroll
        for (int c = 0; c < 4; ++c) {
            float e = __expf(sc[r][c] - mx);
            sc[r][c] = e;
            sum += e;
        }
        #pragma unroll
        for (int off = 8; off >= 1; off >>= 1)
            sum += __shfl_xor_sync(0xffffffffu, sum, off);
        const float inv = 1.0f / sum;
        #pragma unroll
        for (int c = 0; c < 4; ++c) qs[i0 + r][tx + 16 * c] = sc[r][c] * inv;
    }

    // load V into kb (k no longer needed)
    #pragma unroll
    for (int i = 0; i < 4; ++i) {
        const int l = tid + i * 256;
        const int h = l >> 4;
        const int dc = (l & 15) * 4;
        *(float4*)&kb[h][dc] = *(const float4*)(Vp + h * 64 + dc);
    }
    __syncthreads();

    float vv[4][4];
    #pragma unroll
    for (int r = 0; r < 4; ++r)
        #pragma unroll
        for (int c = 0; c < 4; ++c) vv[r][c] = 0.0f;

    #pragma unroll
    for (int k4 = 0; k4 < 16; ++k4) {
        float4 av[4], vb[4];
        #pragma unroll
        for (int r = 0; r < 4; ++r) av[r] = *(const float4*)&qs[i0 + r][k4 * 4];
        #pragma unroll
        for (int c = 0; c < 4; ++c) vb[c] = *(const float4*)&kb[tx + 16 * c][k4 * 4];
        #pragma unroll
        for (int r = 0; r < 4; ++r)
            #pragma unroll
            for (int c = 0; c < 4; ++c)
                vv[r][c] += av[r].x * vb[c].x + av[r].y * vb[c].y +
                            av[r].z * vb[c].z + av[r].w * vb[c].w;
    }

    #pragma unroll
    for (int r = 0; r < 4; ++r)
        #pragma unroll
        for (int c = 0; c < 4; ++c)
            merged[(size_t)(b * 64 + i0 + r) * DFEAT + s * 64 + tx + 16 * c] = vv[r][c];
}

extern "C" void kernel_launch(void* const* d_in, const int* in_sizes, int n_in,
                              void* d_out, int out_size) {
    const float* x  = (const float*)d_in[0];
    const float* Wq = (const float*)d_in[1];
    const float* bq = (const float*)d_in[2];
    const float* Wk = (const float*)d_in[3];
    const float* bk = (const float*)d_in[4];
    const float* Wv = (const float*)d_in[5];
    const float* bv = (const float*)d_in[6];
    const float* Wp = (const float*)d_in[7];
    const float* bp = (const float*)d_in[8];
    float* out = (float*)d_out;

    float* qkv = nullptr;
    float* merged = nullptr;
    cudaGetSymbolAddress((void**)&qkv, g_qkv);
    cudaGetSymbolAddress((void**)&merged, g_merged);

    // 1) QKV projections (3 GEMMs in one launch via z)
    GemmArgs a1;
    a1.A = x;
    a1.W[0] = Wq; a1.W[1] = Wk; a1.W[2] = Wv;
    a1.bias[0] = bq; a1.bias[1] = bk; a1.bias[2] = bv;
    a1.C[0] = qkv;
    a1.C[1] = qkv + (size_t)NTOK * DFEAT;
    a1.C[2] = qkv + 2ull * NTOK * DFEAT;
    gemm_kernel<<<dim3(DFEAT / BN, NTOK / BM, 3), 256>>>(a1);

    // 2) per-token attention -> merged (already in transposed/merged layout)
    attn_kernel<<<NTOK, 256>>>(qkv, merged);

    // 3) output projection
    GemmArgs a2;
    a2.A = merged;
    a2.W[0] = Wp; a2.W[1] = Wp; a2.W[2] = Wp;
    a2.bias[0] = bp; a2.bias[1] = bp; a2.bias[2] = bp;
    a2.C[0] = out; a2.C[1] = out; a2.C[2] = out;
    gemm_kernel<<<dim3(DFEAT / BN, NTOK / BM, 1), 256>>>(a2);
}

// round 3
// speedup vs baseline: 1.2988x; 1.2988x over previous
#include <cuda_runtime.h>
#include <cuda_bf16.h>
#include <stdint.h>

// Problem constants: B=S=H=DH=64, D = H*DH = 4096
static const int DFEAT = 4096;
static const int NTOK  = 4096;

// GEMM tiling: BM=BN=128, BK=64 (bf16), 3-stage cp.async pipeline
static const int BK   = 64;
static const int NKT  = DFEAT / BK;          // 64
static const int TILE_BYTES  = 128 * 128;    // 128 rows x 64 bf16 = 16KB
static const int STAGE_BYTES = 4 * TILE_BYTES;   // Ah, Al, Bh, Bl = 64KB
static const int SMEM_BYTES  = 3 * STAGE_BYTES;  // 192KB

// Scratch (static device arrays; no allocation allowed)
__device__ float          g_qkv[3ull * (size_t)NTOK * DFEAT];
__device__ __nv_bfloat16  g_xh[(size_t)NTOK * DFEAT];
__device__ __nv_bfloat16  g_xl[(size_t)NTOK * DFEAT];
__device__ __nv_bfloat16  g_wh[4ull * (size_t)DFEAT * DFEAT];
__device__ __nv_bfloat16  g_wl[4ull * (size_t)DFEAT * DFEAT];
__device__ __nv_bfloat16  g_mh[(size_t)NTOK * DFEAT];
__device__ __nv_bfloat16  g_ml[(size_t)NTOK * DFEAT];

struct GArgs {
    const __nv_bfloat16* Ah;
    const __nv_bfloat16* Al;
    const __nv_bfloat16* Bh[3];
    const __nv_bfloat16* Bl[3];
    const float*         bias[3];
    float*               C[3];
};

// ---------------- helpers ----------------
__device__ __forceinline__ uint32_t smem_u32(const void* p) {
    uint32_t a;
    asm("{ .reg .u64 t; cvta.to.shared.u64 t, %1; cvt.u32.u64 %0, t; }" : "=r"(a) : "l"(p));
    return a;
}
__device__ __forceinline__ void cp16(uint32_t dst, const void* src) {
    asm volatile("cp.async.cg.shared.global [%0], [%1], 16;" :: "r"(dst), "l"(src) : "memory");
}
__device__ __forceinline__ void cp_commit() {
    asm volatile("cp.async.commit_group;" ::: "memory");
}
template <int N>
__device__ __forceinline__ void cp_wait() {
    asm volatile("cp.async.wait_group %0;" :: "n"(N) : "memory");
}
__device__ __forceinline__ void ldsm4(uint32_t* r, uint32_t a) {
    asm volatile("ldmatrix.sync.aligned.m8n8.x4.shared.b16 {%0,%1,%2,%3}, [%4];"
                 : "=r"(r[0]), "=r"(r[1]), "=r"(r[2]), "=r"(r[3]) : "r"(a));
}
__device__ __forceinline__ void mma_bf16(float c[4], const uint32_t a[4], const uint32_t b[2]) {
    asm volatile(
        "mma.sync.aligned.m16n8k16.row.col.f32.bf16.bf16.f32 "
        "{%0,%1,%2,%3}, {%4,%5,%6,%7}, {%8,%9}, {%0,%1,%2,%3};\n"
        : "+f"(c[0]), "+f"(c[1]), "+f"(c[2]), "+f"(c[3])
        : "r"(a[0]), "r"(a[1]), "r"(a[2]), "r"(a[3]), "r"(b[0]), "r"(b[1]));
}

// ---------------- fp32 -> bf16 hi/lo split ----------------
__global__ __launch_bounds__(256) void split_kernel(const float* __restrict__ src,
                                                    __nv_bfloat16* __restrict__ hi,
                                                    __nv_bfloat16* __restrict__ lo,
                                                    int n4) {
    const float4* s4 = (const float4*)src;
    uint2* h2 = (uint2*)hi;
    uint2* l2 = (uint2*)lo;
    int i = blockIdx.x * blockDim.x + threadIdx.x;
    const int stride = gridDim.x * blockDim.x;
    for (; i < n4; i += stride) {
        float4 v = s4[i];
        __nv_bfloat16 h0 = __float2bfloat16(v.x);
        __nv_bfloat16 h1 = __float2bfloat16(v.y);
        __nv_bfloat16 h2v = __float2bfloat16(v.z);
        __nv_bfloat16 h3 = __float2bfloat16(v.w);
        __nv_bfloat16 l0 = __float2bfloat16(v.x - __bfloat162float(h0));
        __nv_bfloat16 l1 = __float2bfloat16(v.y - __bfloat162float(h1));
        __nv_bfloat16 l2v = __float2bfloat16(v.z - __bfloat162float(h2v));
        __nv_bfloat16 l3 = __float2bfloat16(v.w - __bfloat162float(h3));
        uint2 hp, lp;
        hp.x = (uint32_t)__bfloat16_as_ushort(h0) | ((uint32_t)__bfloat16_as_ushort(h1) << 16);
        hp.y = (uint32_t)__bfloat16_as_ushort(h2v) | ((uint32_t)__bfloat16_as_ushort(h3) << 16);
        lp.x = (uint32_t)__bfloat16_as_ushort(l0) | ((uint32_t)__bfloat16_as_ushort(l1) << 16);
        lp.y = (uint32_t)__bfloat16_as_ushort(l2v) | ((uint32_t)__bfloat16_as_ushort(l3) << 16);
        h2[i] = hp;
        l2[i] = lp;
    }
}

// ---------------- bf16x3 HMMA GEMM ----------------
// C[m][n] = sum_k A[m][k]*B[n][k] + bias[n]; A,B pre-split into bf16 hi/lo.
// 256 threads, warp grid 2(M) x 4(N), warp tile 64x32, BM=BN=128, BK=64.
__global__ __launch_bounds__(256, 1) void gemm_hmma(GArgs g) {
    extern __shared__ __align__(1024) char smem[];
    const int z = blockIdx.z;
    const __nv_bfloat16* __restrict__ Ah = g.Ah;
    const __nv_bfloat16* __restrict__ Al = g.Al;
    const __nv_bfloat16* __restrict__ Bh = g.Bh[z];
    const __nv_bfloat16* __restrict__ Bl = g.Bl[z];
    const float* __restrict__ bias = g.bias[z];
    float* __restrict__ C = g.C[z];

    const int tid  = threadIdx.x;
    const int lane = tid & 31;
    const int wid  = tid >> 5;
    const int wm = (wid & 1) * 64;
    const int wn = (wid >> 1) * 32;
    const int m0 = blockIdx.y * 128;
    const int n0 = blockIdx.x * 128;
    const uint32_t sb = smem_u32(smem);

    // ---- loader mapping: 4 ids per thread, each id = one 16B chunk per tile ----
    uint32_t doff[4];
    int      goff[4];
    #pragma unroll
    for (int i = 0; i < 4; ++i) {
        const int id = tid + i * 256;
        const int r  = id >> 3;      // 0..127
        const int c  = id & 7;       // chunk16
        doff[i] = (uint32_t)(r * 128 + ((c ^ (r & 7)) << 4));
        goff[i] = r * DFEAT + c * 8; // element offset
    }
    const __nv_bfloat16* pAh = Ah + (size_t)m0 * DFEAT;
    const __nv_bfloat16* pAl = Al + (size_t)m0 * DFEAT;
    const __nv_bfloat16* pBh = Bh + (size_t)n0 * DFEAT;
    const __nv_bfloat16* pBl = Bl + (size_t)n0 * DFEAT;

    // ---- ldmatrix lane mapping ----
    uint32_t aoff[4], amask[4];
    const int asel = lane >> 4;  // chunk select
    #pragma unroll
    for (int mt = 0; mt < 4; ++mt) {
        const int rowA = wm + mt * 16 + (((lane >> 3) & 1) << 3) + (lane & 7);
        aoff[mt]  = (uint32_t)(rowA * 128);
        amask[mt] = (uint32_t)((rowA & 7) << 4);
    }
    uint32_t boff[2], bmask[2];
    const int bsel = (lane >> 3) & 1;
    #pragma unroll
    for (int p = 0; p < 2; ++p) {
        const int nrow = wn + p * 16 + ((lane >> 4) << 3) + (lane & 7);
        boff[p]  = (uint32_t)(nrow * 128);
        bmask[p] = (uint32_t)((nrow & 7) << 4);
    }

    float acc[4][4][4];
    #pragma unroll
    for (int a = 0; a < 4; ++a)
        #pragma unroll
        for (int b = 0; b < 4; ++b)
            #pragma unroll
            for (int c = 0; c < 4; ++c) acc[a][b][c] = 0.0f;

    // ---- prologue: fill 3 stages ----
    #pragma unroll
    for (int s = 0; s < 3; ++s) {
        const uint32_t st = sb + s * STAGE_BYTES;
        const int ko = s * BK;
        #pragma unroll
        for (int i = 0; i < 4; ++i) {
            cp16(st + doff[i],                   pAh + goff[i] + ko);
            cp16(st + TILE_BYTES + doff[i],      pAl + goff[i] + ko);
            cp16(st + 2 * TILE_BYTES + doff[i],  pBh + goff[i] + ko);
            cp16(st + 3 * TILE_BYTES + doff[i],  pBl + goff[i] + ko);
        }
        cp_commit();
    }

    for (int kt = 0; kt < NKT; ++kt) {
        if (kt < NKT - 2)       cp_wait<2>();
        else if (kt == NKT - 2) cp_wait<1>();
        else                    cp_wait<0>();
        __syncthreads();

        const uint32_t st  = sb + (kt % 3) * STAGE_BYTES;
        const uint32_t stA = st;
        const uint32_t stAl2 = st + TILE_BYTES;
        const uint32_t stB = st + 2 * TILE_BYTES;
        const uint32_t stBl2 = st + 3 * TILE_BYTES;

        #pragma unroll
        for (int k16 = 0; k16 < 4; ++k16) {
            const uint32_t ka = (uint32_t)((2 * k16 + asel) << 4);
            const uint32_t kb = (uint32_t)((2 * k16 + bsel) << 4);
            uint32_t ah[4][4], al[4][4], bh[2][4], bl[2][4];
            #pragma unroll
            for (int mt = 0; mt < 4; ++mt) {
                ldsm4(ah[mt], stA   + aoff[mt] + (ka ^ amask[mt]));
                ldsm4(al[mt], stAl2 + aoff[mt] + (ka ^ amask[mt]));
            }
            #pragma unroll
            for (int p = 0; p < 2; ++p) {
                ldsm4(bh[p], stB   + boff[p] + (kb ^ bmask[p]));
                ldsm4(bl[p], stBl2 + boff[p] + (kb ^ bmask[p]));
            }
            #pragma unroll
            for (int mt = 0; mt < 4; ++mt) {
                #pragma unroll
                for (int nt = 0; nt < 4; ++nt) {
                    const int p = nt >> 1;
                    const int h = (nt & 1) * 2;
                    mma_bf16(acc[mt][nt], ah[mt], &bh[p][h]);  // hi*hi
                    mma_bf16(acc[mt][nt], ah[mt], &bl[p][h]);  // hi*lo
                    mma_bf16(acc[mt][nt], al[mt], &bh[p][h]);  // lo*hi
                }
            }
        }
        __syncthreads();

        if (kt + 3 < NKT) {
            const int ko = (kt + 3) * BK;
            #pragma unroll
            for (int i = 0; i < 4; ++i) {
                cp16(st + doff[i],                  pAh + goff[i] + ko);
                cp16(st + TILE_BYTES + doff[i],     pAl + goff[i] + ko);
                cp16(st + 2 * TILE_BYTES + doff[i], pBh + goff[i] + ko);
                cp16(st + 3 * TILE_BYTES + doff[i], pBl + goff[i] + ko);
            }
            cp_commit();
        }
    }

    // ---- epilogue ----
    #pragma unroll
    for (int mt = 0; mt < 4; ++mt) {
        const int row = m0 + wm + mt * 16 + (lane >> 2);
        #pragma unroll
        for (int nt = 0; nt < 4; ++nt) {
            const int col = n0 + wn + nt * 8 + (lane & 3) * 2;
            const float2 bb = *(const float2*)&bias[col];
            *(float2*)&C[(size_t)row * DFEAT + col] =
                make_float2(acc[mt][nt][0] + bb.x, acc[mt][nt][1] + bb.y);
            *(float2*)&C[(size_t)(row + 8) * DFEAT + col] =
                make_float2(acc[mt][nt][2] + bb.x, acc[mt][nt][3] + bb.y);
        }
    }
}

// ---------------- per-token attention (outputs bf16 hi/lo merged) ----------------
__global__ __launch_bounds__(256) void attn_kernel(const float* __restrict__ qkv,
                                                   __nv_bfloat16* __restrict__ mh,
                                                   __nv_bfloat16* __restrict__ ml) {
    __shared__ float qs[64][64];
    __shared__ float kb[64][68];

    const int m = blockIdx.x;
    const int b = m >> 6;
    const int s = m & 63;
    const int tid = threadIdx.x;

    const float* Qp = qkv + (size_t)m * DFEAT;
    const float* Kp = Qp + (size_t)NTOK * DFEAT;
    const float* Vp = Kp + (size_t)NTOK * DFEAT;

    #pragma unroll
    for (int i = 0; i < 4; ++i) {
        const int l = tid + i * 256;
        const int h = l >> 4;
        const int dc = (l & 15) * 4;
        *(float4*)&qs[h][dc] = *(const float4*)(Qp + h * 64 + dc);
        *(float4*)&kb[h][dc] = *(const float4*)(Kp + h * 64 + dc);
    }
    __syncthreads();

    const int ty = tid >> 4;
    const int tx = tid & 15;
    const int i0 = ty * 4;

    float sc[4][4];
    #pragma unroll
    for (int r = 0; r < 4; ++r)
        #pragma unroll
        for (int c = 0; c < 4; ++c) sc[r][c] = 0.0f;

    #pragma unroll
    for (int d4 = 0; d4 < 16; ++d4) {
        float4 qv[4], kv[4];
        #pragma unroll
        for (int r = 0; r < 4; ++r) qv[r] = *(const float4*)&qs[i0 + r][d4 * 4];
        #pragma unroll
        for (int c = 0; c < 4; ++c) kv[c] = *(const float4*)&kb[tx + 16 * c][d4 * 4];
        #pragma unroll
        for (int r = 0; r < 4; ++r)
            #pragma unroll
            for (int c = 0; c < 4; ++c)
                sc[r][c] += qv[r].x * kv[c].x + qv[r].y * kv[c].y +
                            qv[r].z * kv[c].z + qv[r].w * kv[c].w;
    }
    __syncthreads();

    #pragma unroll
    for (int r = 0; r < 4; ++r) {
        #pragma unroll
        for (int c = 0; c < 4; ++c) sc[r][c] *= 0.125f;
        float mx = fmaxf(fmaxf(sc[r][0], sc[r][1]), fmaxf(sc[r][2], sc[r][3]));
        #pragma unroll
        for (int off = 8; off >= 1; off >>= 1)
            mx = fmaxf(mx, __shfl_xor_sync(0xffffffffu, mx, off));
        float sum = 0.0f;
        #pragma unroll
        for (int c = 0; c < 4; ++c) {
            float e = __expf(sc[r][c] - mx);
            sc[r][c] = e;
            sum += e;
        }
        #pragma unroll
        for (int off = 8; off >= 1; off >>= 1)
            sum += __shfl_xor_sync(0xffffffffu, sum, off);
        const float inv = 1.0f / sum;
        #pragma unroll
        for (int c = 0; c < 4; ++c) qs[i0 + r][tx + 16 * c] = sc[r][c] * inv;
    }

    #pragma unroll
    for (int i = 0; i < 4; ++i) {
        const int l = tid + i * 256;
        const int h = l >> 4;
        const int dc = (l & 15) * 4;
        *(float4*)&kb[h][dc] = *(const float4*)(Vp + h * 64 + dc);
    }
    __syncthreads();

    float vv[4][4];
    #pragma unroll
    for (int r = 0; r < 4; ++r)
        #pragma unroll
        for (int c = 0; c < 4; ++c) vv[r][c] = 0.0f;

    #pragma unroll
    for (int k4 = 0; k4 < 16; ++k4) {
        float4 av[4], vb[4];
        #pragma unroll
        for (int r = 0; r < 4; ++r) av[r] = *(const float4*)&qs[i0 + r][k4 * 4];
        #pragma unroll
        for (int c = 0; c < 4; ++c) vb[c] = *(const float4*)&kb[tx + 16 * c][k4 * 4];
        #pragma unroll
        for (int r = 0; r < 4; ++r)
            #pragma unroll
            for (int c = 0; c < 4; ++c)
                vv[r][c] += av[r].x * vb[c].x + av[r].y * vb[c].y +
                            av[r].z * vb[c].z + av[r].w * vb[c].w;
    }

    #pragma unroll
    for (int r = 0; r < 4; ++r) {
        #pragma unroll
        for (int c = 0; c < 4; ++c) {
            const float v = vv[r][c];
            const __nv_bfloat16 h = __float2bfloat16(v);
            const __nv_bfloat16 l = __float2bfloat16(v - __bfloat162float(h));
            const size_t off = (size_t)(b * 64 + i0 + r) * DFEAT + s * 64 + tx + 16 * c;
            mh[off] = h;
            ml[off] = l;
        }
    }
}

extern "C" void kernel_launch(void* const* d_in, const int* in_sizes, int n_in,
                              void* d_out, int out_size) {
    const float* x  = (const float*)d_in[0];
    const float* Wq = (const float*)d_in[1];
    const float* bq = (const float*)d_in[2];
    const float* Wk = (const float*)d_in[3];
    const float* bk = (const float*)d_in[4];
    const float* Wv = (const float*)d_in[5];
    const float* bv = (const float*)d_in[6];
    const float* Wp = (const float*)d_in[7];
    const float* bp = (const float*)d_in[8];
    float* out = (float*)d_out;

    float* qkv = nullptr;
    __nv_bfloat16 *xh, *xl, *wh, *wl, *mh, *ml;
    cudaGetSymbolAddress((void**)&qkv, g_qkv);
    cudaGetSymbolAddress((void**)&xh, g_xh);
    cudaGetSymbolAddress((void**)&xl, g_xl);
    cudaGetSymbolAddress((void**)&wh, g_wh);
    cudaGetSymbolAddress((void**)&wl, g_wl);
    cudaGetSymbolAddress((void**)&mh, g_mh);
    cudaGetSymbolAddress((void**)&ml, g_ml);

    cudaFuncSetAttribute(gemm_hmma, cudaFuncAttributeMaxDynamicSharedMemorySize, SMEM_BYTES);

    const size_t MSZ = (size_t)DFEAT * DFEAT;  // 16.7M elements
    const int n4 = (int)(MSZ / 4);

    // 0) split inputs into bf16 hi/lo
    split_kernel<<<2048, 256>>>(x,  xh,          xl,          n4);
    split_kernel<<<2048, 256>>>(Wq, wh,          wl,          n4);
    split_kernel<<<2048, 256>>>(Wk, wh + MSZ,    wl + MSZ,    n4);
    split_kernel<<<2048, 256>>>(Wv, wh + 2*MSZ,  wl + 2*MSZ,  n4);
    split_kernel<<<2048, 256>>>(Wp, wh + 3*MSZ,  wl + 3*MSZ,  n4);

    // 1) QKV projections
    GArgs a1;
    a1.Ah = xh; a1.Al = xl;
    a1.Bh[0] = wh;           a1.Bl[0] = wl;
    a1.Bh[1] = wh + MSZ;     a1.Bl[1] = wl + MSZ;
    a1.Bh[2] = wh + 2*MSZ;   a1.Bl[2] = wl + 2*MSZ;
    a1.bias[0] = bq; a1.bias[1] = bk; a1.bias[2] = bv;
    a1.C[0] = qkv;
    a1.C[1] = qkv + (size_t)NTOK * DFEAT;
    a1.C[2] = qkv + 2ull * NTOK * DFEAT;
    gemm_hmma<<<dim3(32, 32, 3), 256, SMEM_BYTES>>>(a1);

    // 2) per-token attention -> merged (bf16 hi/lo)
    attn_kernel<<<NTOK, 256>>>(qkv, mh, ml);

    // 3) output projection
    GArgs a2;
    a2.Ah = mh; a2.Al = ml;
    a2.Bh[0] = wh + 3*MSZ; a2.Bl[0] = wl + 3*MSZ;
    a2.Bh[1] = wh + 3*MSZ; a2.Bl[1] = wl + 3*MSZ;
    a2.Bh[2] = wh + 3*MSZ; a2.Bl[2] = wl + 3*MSZ;
    a2.bias[0] = bp; a2.bias[1] = bp; a2.bias[2] = bp;
    a2.C[0] = out; a2.C[1] = out; a2.C[2] = out;
    gemm_hmma<<<dim3(32, 32, 1), 256, SMEM_BYTES>>>(a2);
}